// round 1
// baseline (speedup 1.0000x reference)
#include <cuda_runtime.h>

// SCM_19061064860184: 4 directional conv-scans over [8,1,1024,1024] fp32.
//
// Key reductions:
//  - each 5x5 conv degenerates to a 5-tap 1D conv (spatial plane has one dim == 1)
//  - passes 1+2 fuse (pass 2 consumes pass-1 states in production order), u lags s
//    by one tick -> 1 __syncthreads per tick; same for passes 3+4
//  - batches independent -> 1 persistent CTA per batch, 1024 threads (1 position each)
//  - u-states staged 32 rows at a time in smem, flushed transposed+reversed with
//    coalesced stores into a __device__ scratch; second scan reads rows directly.

#define NN 1024   // positions per scan line
#define TT 1024   // ticks (scan length)

struct Smem {
    float sb[2][NN + 4];        // s-state double buffer, value v[q] at [q+2], zero guards
    float ub[2][NN + 4];        // u-state double buffer
    float xb[2][NN + 4];        // input-row double buffer
    float stage[32][NN + 1];    // 32 u-rows staged for transposed flush (+1 pad: conflict-free column reads)
};

__device__ float g_scratch[8 * NN * TT];   // 32 MB inter-phase scratch (out2, transposed layout)

__device__ __forceinline__ float conv5(const float* __restrict__ a, int p,
                                       float t0, float t1, float t2, float t3, float t4)
{
    // a holds values offset by +2; returns sum_k t_k * v[p+k-2]
    float r = t0 * a[p];
    r = fmaf(t1, a[p + 1], r);
    r = fmaf(t2, a[p + 2], r);
    r = fmaf(t3, a[p + 3], r);
    r = fmaf(t4, a[p + 4], r);
    return r;
}

// One fused scan pair: s_t = preA(IN[0]) / stepA(s_{t-1}, IN[t]);
//                      u_t = preB(s_0)  / stepB(u_{t-1}, s_t).
// Writes u_t to OUT[p][NN-1-t] (transposed + reversed), coalesced via smem staging.
// colTaps=0: taps w[0,cin,2,k] (along W). colTaps=1: taps w[0,cin,k,2] (along H).
__device__ __forceinline__ void fused_scan(
    Smem* __restrict__ sm,
    const float* __restrict__ IN, float* __restrict__ OUT,
    const float* __restrict__ preAw, const float* __restrict__ preAb,
    const float* __restrict__ cAw,   const float* __restrict__ cAb,
    const float* __restrict__ preBw, const float* __restrict__ preBb,
    const float* __restrict__ cBw,   const float* __restrict__ cBb,
    int colTaps)
{
    const int tid = threadIdx.x;
    const int p = tid;

    // tap flat-index: row-2 taps (10+k) for W scans, col-2 taps (5k+2) for H scans
    #define TI(k) (colTaps ? (5 * (k) + 2) : (10 + (k)))

    const float aS0 = cAw[TI(0)], aS1 = cAw[TI(1)], aS2 = cAw[TI(2)], aS3 = cAw[TI(3)], aS4 = cAw[TI(4)];
    const float aX0 = cAw[25 + TI(0)], aX1 = cAw[25 + TI(1)], aX2 = cAw[25 + TI(2)], aX3 = cAw[25 + TI(3)], aX4 = cAw[25 + TI(4)];
    const float bA  = cAb[0];
    const float bS0 = cBw[TI(0)], bS1 = cBw[TI(1)], bS2 = cBw[TI(2)], bS3 = cBw[TI(3)], bS4 = cBw[TI(4)];
    const float bX0 = cBw[25 + TI(0)], bX1 = cBw[25 + TI(1)], bX2 = cBw[25 + TI(2)], bX3 = cBw[25 + TI(3)], bX4 = cBw[25 + TI(4)];
    const float bB  = cBb[0];

    // zero the +/-2 guard cells once (never written during ticks)
    if (tid < 2) {
        #pragma unroll
        for (int q = 0; q < 2; ++q) {
            sm->sb[q][tid] = 0.f; sm->sb[q][NN + 2 + tid] = 0.f;
            sm->ub[q][tid] = 0.f; sm->ub[q][NN + 2 + tid] = 0.f;
            sm->xb[q][tid] = 0.f; sm->xb[q][NN + 2 + tid] = 0.f;
        }
    }
    sm->xb[0][p + 2] = IN[p];            // row 0
    float x_r = IN[NN + p];              // register prefetch of row 1
    __syncthreads();

    #pragma unroll 1
    for (int t = 0; t <= TT; ++t) {
        // stage the register-prefetched row (needed NEXT tick), then prefetch 2 ahead
        if (t + 1 < TT) sm->xb[(t + 1) & 1][p + 2] = x_r;
        if (t + 2 < TT) x_r = IN[(size_t)(t + 2) * NN + p];

        // --- s-recurrence: s_t ---
        if (t < TT) {
            const float* xc = sm->xb[t & 1];
            float s_new;
            if (t == 0) {
                float w0 = preAw[TI(0)], w1 = preAw[TI(1)], w2 = preAw[TI(2)], w3 = preAw[TI(3)], w4 = preAw[TI(4)];
                s_new = preAb[0] + conv5(xc, p, w0, w1, w2, w3, w4);
            } else {
                const float* sp = sm->sb[(t - 1) & 1];
                s_new = bA + conv5(sp, p, aS0, aS1, aS2, aS3, aS4)
                           + conv5(xc, p, aX0, aX1, aX2, aX3, aX4);
            }
            sm->sb[t & 1][p + 2] = s_new;
        }

        // --- u-recurrence (lagged one tick): u_{t-1} ---
        if (t >= 1) {
            const float* sp = sm->sb[(t - 1) & 1];   // s_{t-1}, written last tick
            float u_new;
            if (t == 1) {
                float w0 = preBw[TI(0)], w1 = preBw[TI(1)], w2 = preBw[TI(2)], w3 = preBw[TI(3)], w4 = preBw[TI(4)];
                u_new = preBb[0] + conv5(sp, p, w0, w1, w2, w3, w4);
            } else {
                const float* up = sm->ub[(t - 1) & 1];  // u_{t-2}
                u_new = bB + conv5(up, p, bS0, bS1, bS2, bS3, bS4)
                           + conv5(sp, p, bX0, bX1, bX2, bX3, bX4);
            }
            sm->ub[t & 1][p + 2] = u_new;
            sm->stage[(t - 1) & 31][p] = u_new;
        }

        __syncthreads();

        // --- flush 32 staged u-rows, transposed + reversed, fully coalesced ---
        if (t >= 32 && ((t - 1) & 31) == 31) {
            const int i0 = t - 32;                 // first u-index of the group
            const int wp = tid >> 5, l = tid & 31;
            const int col = NN - 1 - (i0 + l);     // lanes -> descending consecutive addrs
            #pragma unroll 8
            for (int r = 0; r < 32; ++r) {
                const int row = wp * 32 + r;       // warp wp owns rows [32wp, 32wp+32)
                OUT[(size_t)row * NN + col] = sm->stage[l][row];  // pad-1 => conflict-free
            }
            __syncthreads();
        }
    }
    #undef TI
}

__global__ void __launch_bounds__(1024, 1)
scm_kernel(const float* __restrict__ x, float* __restrict__ out,
           const float* p1w, const float* p1b, const float* p2w, const float* p2b,
           const float* p3w, const float* p3b, const float* p4w, const float* p4b,
           const float* c1w, const float* c1b, const float* c2w, const float* c2b,
           const float* c3w, const float* c3b, const float* c4w, const float* c4b)
{
    extern __shared__ char raw[];
    Smem* sm = reinterpret_cast<Smem*>(raw);
    const int b = blockIdx.x;

    const float* xin = x + (size_t)b * NN * TT;
    float* scr       = g_scratch + (size_t)b * NN * TT;
    float* o         = out + (size_t)b * NN * TT;

    // phase A: passes 1+2 (scan over h, taps along W). scr[w][j] = u_{H-1-j}[w] = out2[b,j,w]
    fused_scan(sm, xin, scr, p1w, p1b, c1w, c1b, p2w, p2b, c2w, c2b, /*colTaps=*/0);
    __syncthreads();   // scr writes visible to this CTA

    // phase B: passes 3+4 (scan over w, taps along H). reads scr rows; writes
    // out[b,0,h,W-1-t] = z_t[h] via the same transposed flush.
    fused_scan(sm, scr, o, p3w, p3b, c3w, c3b, p4w, p4b, c4w, c4b, /*colTaps=*/1);
}

extern "C" void kernel_launch(void* const* d_in, const int* in_sizes, int n_in,
                              void* d_out, int out_size)
{
    (void)in_sizes; (void)n_in; (void)out_size;
    const float* x   = (const float*)d_in[0];
    const float* p1w = (const float*)d_in[1];
    const float* p1b = (const float*)d_in[2];
    const float* p2w = (const float*)d_in[3];
    const float* p2b = (const float*)d_in[4];
    const float* p3w = (const float*)d_in[5];
    const float* p3b = (const float*)d_in[6];
    const float* p4w = (const float*)d_in[7];
    const float* p4b = (const float*)d_in[8];
    const float* c1w = (const float*)d_in[9];
    const float* c1b = (const float*)d_in[10];
    const float* c2w = (const float*)d_in[11];
    const float* c2b = (const float*)d_in[12];
    const float* c3w = (const float*)d_in[13];
    const float* c3b = (const float*)d_in[14];
    const float* c4w = (const float*)d_in[15];
    const float* c4b = (const float*)d_in[16];

    cudaFuncSetAttribute(scm_kernel, cudaFuncAttributeMaxDynamicSharedMemorySize,
                         (int)sizeof(Smem));
    scm_kernel<<<8, 1024, sizeof(Smem)>>>(
        x, (float*)d_out,
        p1w, p1b, p2w, p2b, p3w, p3b, p4w, p4b,
        c1w, c1b, c2w, c2b, c3w, c3b, c4w, c4b);
}

// round 2
// speedup vs baseline: 1.2077x; 1.2077x over previous
#include <cuda_runtime.h>

// SCM_19061064860184 — register-resident fused directional conv-scans.
// 8 CTAs (one per batch) x 256 threads; each thread owns 4 consecutive positions.
// State arrays s (pass-A state), u (pass-B state), x (input row) live in registers;
// 5-tap halos come from warp shuffles + tiny smem slots at warp boundaries.

#define NN   1024
#define TT   1024
#define NTH  256
#define NW   8
#define FULLM 0xffffffffu

struct Smem {
    float2 bnd[2][3][2][NW + 2];   // [buf][array 0=s,1=u,2=x][side 0=L,1=R][warp slot]
    float  stage[32][NN + 1];      // 32 u-rows staged for transposed+reversed flush
};

__device__ float g_scratch[8 * NN * TT];   // 32 MB inter-phase scratch

// accumulate 5-tap conv at 4 consecutive positions into a0..a3
__device__ __forceinline__ void acc4(
    float& a0, float& a1, float& a2, float& a3,
    float L2, float L1, float v0, float v1, float v2, float v3, float R0, float R1,
    float t0, float t1, float t2, float t3, float t4)
{
    a0 = fmaf(t0, L2, a0); a0 = fmaf(t1, L1, a0); a0 = fmaf(t2, v0, a0); a0 = fmaf(t3, v1, a0); a0 = fmaf(t4, v2, a0);
    a1 = fmaf(t0, L1, a1); a1 = fmaf(t1, v0, a1); a1 = fmaf(t2, v1, a1); a1 = fmaf(t3, v2, a1); a1 = fmaf(t4, v3, a1);
    a2 = fmaf(t0, v0, a2); a2 = fmaf(t1, v1, a2); a2 = fmaf(t2, v2, a2); a2 = fmaf(t3, v3, a2); a2 = fmaf(t4, R0, a2);
    a3 = fmaf(t0, v1, a3); a3 = fmaf(t1, v2, a3); a3 = fmaf(t2, v3, a3); a3 = fmaf(t3, R0, a3); a3 = fmaf(t4, R1, a3);
}

// fetch +/-2 halo of a register-resident array (shuffles + warp-boundary smem)
#define HALO(arr, v0, v1, v2, v3, L2, L1, R0, R1, buf) do {               \
    L1 = __shfl_up_sync(FULLM, v3, 1);                                    \
    L2 = __shfl_up_sync(FULLM, v2, 1);                                    \
    R0 = __shfl_down_sync(FULLM, v0, 1);                                  \
    R1 = __shfl_down_sync(FULLM, v1, 1);                                  \
    if (lane == 0)  { float2 h_ = sm->bnd[buf][arr][1][w];     L2 = h_.x; L1 = h_.y; } \
    if (lane == 31) { float2 h_ = sm->bnd[buf][arr][0][w + 2]; R0 = h_.x; R1 = h_.y; } \
} while (0)

// publish this warp's boundary values for next tick
#define BSTORE(arr, v0, v1, v2, v3, buf) do {                             \
    if (lane == 0)  sm->bnd[buf][arr][0][w + 1] = make_float2(v0, v1);    \
    if (lane == 31) sm->bnd[buf][arr][1][w + 1] = make_float2(v2, v3);    \
} while (0)

// flush 32 staged u-rows, transposed + reversed, float4 coalesced stores.
// lane mapping: q = uidx quad, rows strided; LDS banks (4q+j+row)%32 = permutation.
__device__ __forceinline__ void flush32(Smem* __restrict__ sm, float* __restrict__ OUT,
                                        int i0, int tid)
{
    const int q = tid & 7;
    const int r0 = tid >> 3;
    const int cbase = NN - 4 - i0 - 4 * q;     // col of uidx i0+4q+3
    const float* s0 = sm->stage[4 * q + 0];
    const float* s1 = sm->stage[4 * q + 1];
    const float* s2 = sm->stage[4 * q + 2];
    const float* s3 = sm->stage[4 * q + 3];
    #pragma unroll 8
    for (int k = 0; k < 32; ++k) {
        const int row = r0 + (k << 5);
        float4 v = make_float4(s3[row], s2[row], s1[row], s0[row]);
        *reinterpret_cast<float4*>(OUT + (size_t)row * NN + cbase) = v;
    }
}

template <int COLTAPS>
__device__ __forceinline__ void fused_scan(
    Smem* __restrict__ sm,
    const float* __restrict__ IN, float* __restrict__ OUT,
    const float* __restrict__ preAw, const float* __restrict__ preAb,
    const float* __restrict__ cAw,   const float* __restrict__ cAb,
    const float* __restrict__ preBw, const float* __restrict__ preBb,
    const float* __restrict__ cBw,   const float* __restrict__ cBb)
{
    const int tid  = threadIdx.x;
    const int w    = tid >> 5;
    const int lane = tid & 31;
    const int base = tid << 2;

    // tap flat-index: row-2 taps for W scans, col-2 taps for H scans
    #define TI(k) (COLTAPS ? (5 * (k) + 2) : (10 + (k)))

    const float aS0 = cAw[TI(0)], aS1 = cAw[TI(1)], aS2 = cAw[TI(2)], aS3 = cAw[TI(3)], aS4 = cAw[TI(4)];
    const float aX0 = cAw[25 + TI(0)], aX1 = cAw[25 + TI(1)], aX2 = cAw[25 + TI(2)], aX3 = cAw[25 + TI(3)], aX4 = cAw[25 + TI(4)];
    const float bA  = cAb[0];
    const float bS0 = cBw[TI(0)], bS1 = cBw[TI(1)], bS2 = cBw[TI(2)], bS3 = cBw[TI(3)], bS4 = cBw[TI(4)];
    const float bX0 = cBw[25 + TI(0)], bX1 = cBw[25 + TI(1)], bX2 = cBw[25 + TI(2)], bX3 = cBw[25 + TI(3)], bX4 = cBw[25 + TI(4)];
    const float bB  = cBb[0];

    // zero all boundary slots (edge slots stay zero forever => zero padding)
    {
        float2* bz = &sm->bnd[0][0][0][0];
        for (int i = tid; i < 2 * 3 * 2 * (NW + 2); i += NTH)
            bz[i] = make_float2(0.f, 0.f);
    }

    float4 xv = *reinterpret_cast<const float4*>(IN + base);
    float x0 = xv.x, x1 = xv.y, x2 = xv.z, x3 = xv.w;
    float4 xn = *reinterpret_cast<const float4*>(IN + NN + base);
    BSTORE(2, x0, x1, x2, x3, 0);
    __syncthreads();

    float s0, s1, s2, s3, u0, u1, u2, u3;

    // ---- t = 0: s_0 = preA(x_0) ----
    {
        const float p0 = preAw[TI(0)], p1 = preAw[TI(1)], p2 = preAw[TI(2)], p3 = preAw[TI(3)], p4 = preAw[TI(4)];
        const float pb = preAb[0];
        float L2, L1, R0, R1;
        HALO(2, x0, x1, x2, x3, L2, L1, R0, R1, 0);
        float a0 = pb, a1 = pb, a2 = pb, a3 = pb;
        acc4(a0, a1, a2, a3, L2, L1, x0, x1, x2, x3, R0, R1, p0, p1, p2, p3, p4);
        s0 = a0; s1 = a1; s2 = a2; s3 = a3;
        BSTORE(0, s0, s1, s2, s3, 1);
        BSTORE(2, xn.x, xn.y, xn.z, xn.w, 1);
        x0 = xn.x; x1 = xn.y; x2 = xn.z; x3 = xn.w;
        xn = *reinterpret_cast<const float4*>(IN + 2 * NN + base);
        __syncthreads();
    }

    // ---- t = 1: s_1 = stepA(s_0, x_1); u_0 = preB(s_0) ----
    {
        const float q0 = preBw[TI(0)], q1 = preBw[TI(1)], q2 = preBw[TI(2)], q3 = preBw[TI(3)], q4 = preBw[TI(4)];
        const float qb = preBb[0];
        float sL2, sL1, sR0, sR1, L2, L1, R0, R1;
        HALO(0, s0, s1, s2, s3, sL2, sL1, sR0, sR1, 1);
        HALO(2, x0, x1, x2, x3, L2, L1, R0, R1, 1);
        float a0 = bA, a1 = bA, a2 = bA, a3 = bA;
        acc4(a0, a1, a2, a3, sL2, sL1, s0, s1, s2, s3, sR0, sR1, aS0, aS1, aS2, aS3, aS4);
        acc4(a0, a1, a2, a3, L2, L1, x0, x1, x2, x3, R0, R1, aX0, aX1, aX2, aX3, aX4);
        float c0 = qb, c1 = qb, c2 = qb, c3 = qb;
        acc4(c0, c1, c2, c3, sL2, sL1, s0, s1, s2, s3, sR0, sR1, q0, q1, q2, q3, q4);
        u0 = c0; u1 = c1; u2 = c2; u3 = c3;
        s0 = a0; s1 = a1; s2 = a2; s3 = a3;
        sm->stage[0][base + 0] = u0; sm->stage[0][base + 1] = u1;
        sm->stage[0][base + 2] = u2; sm->stage[0][base + 3] = u3;
        BSTORE(0, s0, s1, s2, s3, 0);
        BSTORE(1, u0, u1, u2, u3, 0);
        BSTORE(2, xn.x, xn.y, xn.z, xn.w, 0);
        x0 = xn.x; x1 = xn.y; x2 = xn.z; x3 = xn.w;
        xn = *reinterpret_cast<const float4*>(IN + 3 * NN + base);
        __syncthreads();
    }

    // ---- main loop t = 2 .. TT-1 ----
    #pragma unroll 1
    for (int t = 2; t < TT; ++t) {
        const int b = t & 1, nb = b ^ 1;
        float sL2, sL1, sR0, sR1, xL2, xL1, xR0, xR1, uL2, uL1, uR0, uR1;
        HALO(0, s0, s1, s2, s3, sL2, sL1, sR0, sR1, b);
        HALO(2, x0, x1, x2, x3, xL2, xL1, xR0, xR1, b);
        HALO(1, u0, u1, u2, u3, uL2, uL1, uR0, uR1, b);

        float a0 = bA, a1 = bA, a2 = bA, a3 = bA;              // s_t
        acc4(a0, a1, a2, a3, sL2, sL1, s0, s1, s2, s3, sR0, sR1, aS0, aS1, aS2, aS3, aS4);
        acc4(a0, a1, a2, a3, xL2, xL1, x0, x1, x2, x3, xR0, xR1, aX0, aX1, aX2, aX3, aX4);
        float c0 = bB, c1 = bB, c2 = bB, c3 = bB;              // u_{t-1}
        acc4(c0, c1, c2, c3, uL2, uL1, u0, u1, u2, u3, uR0, uR1, bS0, bS1, bS2, bS3, bS4);
        acc4(c0, c1, c2, c3, sL2, sL1, s0, s1, s2, s3, sR0, sR1, bX0, bX1, bX2, bX3, bX4);

        const int sr = (t - 1) & 31;
        sm->stage[sr][base + 0] = c0; sm->stage[sr][base + 1] = c1;
        sm->stage[sr][base + 2] = c2; sm->stage[sr][base + 3] = c3;

        u0 = c0; u1 = c1; u2 = c2; u3 = c3;
        s0 = a0; s1 = a1; s2 = a2; s3 = a3;
        BSTORE(0, s0, s1, s2, s3, nb);
        BSTORE(1, u0, u1, u2, u3, nb);
        BSTORE(2, xn.x, xn.y, xn.z, xn.w, nb);
        x0 = xn.x; x1 = xn.y; x2 = xn.z; x3 = xn.w;
        {
            int tn = t + 2; if (tn > TT - 1) tn = TT - 1;       // clamped prefetch
            xn = *reinterpret_cast<const float4*>(IN + (size_t)tn * NN + base);
        }
        __syncthreads();

        if ((t & 31) == 0) {
            flush32(sm, OUT, t - 32, tid);
            __syncthreads();
        }
    }

    // ---- t = TT: u_{TT-1} = stepB(u_{TT-2}, s_{TT-1}) ----
    {
        const int b = TT & 1;   // 0
        float sL2, sL1, sR0, sR1, uL2, uL1, uR0, uR1;
        HALO(0, s0, s1, s2, s3, sL2, sL1, sR0, sR1, b);
        HALO(1, u0, u1, u2, u3, uL2, uL1, uR0, uR1, b);
        float c0 = bB, c1 = bB, c2 = bB, c3 = bB;
        acc4(c0, c1, c2, c3, uL2, uL1, u0, u1, u2, u3, uR0, uR1, bS0, bS1, bS2, bS3, bS4);
        acc4(c0, c1, c2, c3, sL2, sL1, s0, s1, s2, s3, sR0, sR1, bX0, bX1, bX2, bX3, bX4);
        sm->stage[31][base + 0] = c0; sm->stage[31][base + 1] = c1;
        sm->stage[31][base + 2] = c2; sm->stage[31][base + 3] = c3;
        __syncthreads();
        flush32(sm, OUT, TT - 32, tid);
        __syncthreads();
    }
    #undef TI
}

__global__ void __launch_bounds__(NTH, 1)
scm_kernel(const float* __restrict__ x, float* __restrict__ out,
           const float* p1w, const float* p1b, const float* p2w, const float* p2b,
           const float* p3w, const float* p3b, const float* p4w, const float* p4b,
           const float* c1w, const float* c1b, const float* c2w, const float* c2b,
           const float* c3w, const float* c3b, const float* c4w, const float* c4b)
{
    extern __shared__ char raw[];
    Smem* sm = reinterpret_cast<Smem*>(raw);
    const int b = blockIdx.x;

    const float* xin = x + (size_t)b * NN * TT;
    float* scr       = g_scratch + (size_t)b * NN * TT;
    float* o         = out + (size_t)b * NN * TT;

    // phase A: passes 1+2 (scan over h, taps along W)
    fused_scan<0>(sm, xin, scr, p1w, p1b, c1w, c1b, p2w, p2b, c2w, c2b);
    __syncthreads();
    // phase B: passes 3+4 (scan over w, taps along H)
    fused_scan<1>(sm, scr, o, p3w, p3b, c3w, c3b, p4w, p4b, c4w, c4b);
}

extern "C" void kernel_launch(void* const* d_in, const int* in_sizes, int n_in,
                              void* d_out, int out_size)
{
    (void)in_sizes; (void)n_in; (void)out_size;
    const float* x   = (const float*)d_in[0];
    const float* p1w = (const float*)d_in[1];
    const float* p1b = (const float*)d_in[2];
    const float* p2w = (const float*)d_in[3];
    const float* p2b = (const float*)d_in[4];
    const float* p3w = (const float*)d_in[5];
    const float* p3b = (const float*)d_in[6];
    const float* p4w = (const float*)d_in[7];
    const float* p4b = (const float*)d_in[8];
    const float* c1w = (const float*)d_in[9];
    const float* c1b = (const float*)d_in[10];
    const float* c2w = (const float*)d_in[11];
    const float* c2b = (const float*)d_in[12];
    const float* c3w = (const float*)d_in[13];
    const float* c3b = (const float*)d_in[14];
    const float* c4w = (const float*)d_in[15];
    const float* c4b = (const float*)d_in[16];

    cudaFuncSetAttribute(scm_kernel, cudaFuncAttributeMaxDynamicSharedMemorySize,
                         (int)sizeof(Smem));
    scm_kernel<<<8, NTH, sizeof(Smem)>>>(
        x, (float*)d_out,
        p1w, p1b, p2w, p2b, p3w, p3b, p4w, p4b,
        c1w, c1b, c2w, c2b, c3w, c3b, c4w, c4b);
}

// round 3
// speedup vs baseline: 1.8096x; 1.4984x over previous
#include <cuda_runtime.h>

// SCM_19061064860184 — barrier-light register scan with redundant halos.
// 8 CTAs x 256 threads. Each warp owns 128 positions + computes a 16-wide halo
// redundantly on each side (window 160 = 5 slots/thread). Exchange through smem
// only every 8 ticks. Phase A's input contribution Y is precomputed by yprep.

#define NN 1024
#define TT 1024
#define NTH 256
#define NW 8
#define OWN 128
#define HB 16
#define SW 1288            // padded stage row width (8 warps * 160 + 8)
#define FULLM 0xffffffffu

struct Smem {
    float sEx[2][NN + 2 * HB];
    float uEx[2][NN + 2 * HB];
    float stage[32][SW];
};

__device__ float g_scr[8 * NN * TT];   // inter-phase scratch (out2, transposed)
__device__ float g_y[8 * NN * TT];     // precomputed Y for phase A

// out[j] += sum_k tp[k] * value(pos g0+j-2+k), window = [L2,L1,v0..v4,R0,R1]
__device__ __forceinline__ void conv5acc(float out[5], const float v[5],
                                         float L2, float L1, float R0, float R1,
                                         const float tp[5])
{
    float win[9] = {L2, L1, v[0], v[1], v[2], v[3], v[4], R0, R1};
    #pragma unroll
    for (int j = 0; j < 5; ++j)
        #pragma unroll
        for (int k = 0; k < 5; ++k)
            out[j] = fmaf(tp[k], win[j + k], out[j]);
}

#define HALO4(v, L2, L1, R0, R1) do {                 \
    L1 = __shfl_up_sync(FULLM, (v)[4], 1);            \
    L2 = __shfl_up_sync(FULLM, (v)[3], 1);            \
    R0 = __shfl_down_sync(FULLM, (v)[0], 1);          \
    R1 = __shfl_down_sync(FULLM, (v)[1], 1);          \
} while (0)

// flush 16 staged u-rows (u-indices i0..i0+15), transposed + reversed, float4 stores
__device__ __forceinline__ void flush16(Smem* __restrict__ sm, float* __restrict__ OUT,
                                        int i0, int tid)
{
    const int sbase = i0 & 31;
    const int q  = tid & 3;
    const int rt = tid >> 2;
    const int cb = NN - 4 - i0 - 4 * q;   // col of u-idx i0+4q+3
    #pragma unroll 4
    for (int k = 0; k < 16; ++k) {
        const int row = rt + (k << 6);
        const int a2  = (row >> 7) * 160 + (row & 127) + HB;  // stage addr of global pos `row`
        float4 v;
        v.x = sm->stage[sbase + 4 * q + 3][a2];
        v.y = sm->stage[sbase + 4 * q + 2][a2];
        v.z = sm->stage[sbase + 4 * q + 1][a2];
        v.w = sm->stage[sbase + 4 * q + 0][a2];
        *reinterpret_cast<float4*>(OUT + (size_t)row * NN + cb) = v;
    }
}

// PHASE 0: s_t = convS_A(s_{t-1}) + R[t]   (R = precomputed Y, includes bias & pre-row)
// PHASE 1: s_0 = preA(R0)+pAb ; s_t = convS_A(s_{t-1}) + convX_A(R[t]) + bA
// both:    u_0 = preB(s_0)+pBb ; u_t = convS_B(u_{t-1}) + convX_B(s_t) + bB
template <int COLTAPS, int PHASE>
__device__ void fused_scan(Smem* __restrict__ sm,
    const float* __restrict__ RIN, float* __restrict__ OUT,
    const float* __restrict__ preBw, const float* __restrict__ preBbp,
    const float* __restrict__ cAw, const float* __restrict__ cAb,
    const float* __restrict__ cBw, const float* __restrict__ cBb,
    const float* __restrict__ preAw, const float* __restrict__ preAbp)
{
    const int tid = threadIdx.x, w = tid >> 5, lane = tid & 31;
#define TI(k) (COLTAPS ? (5 * (k) + 2) : (10 + (k)))
    float aS[5], bS[5], bX[5], pB[5], aX[5], pA[5];
    #pragma unroll
    for (int k = 0; k < 5; ++k) {
        aS[k] = cAw[TI(k)];
        bS[k] = cBw[TI(k)];
        bX[k] = cBw[25 + TI(k)];
        pB[k] = preBw[TI(k)];
        if (PHASE == 1) { aX[k] = cAw[25 + TI(k)]; pA[k] = preAw[TI(k)]; }
        else            { aX[k] = 0.f;             pA[k] = 0.f; }
    }
    const float bA = cAb[0], bB = cBb[0], pBb = preBbp[0];
    const float pAb = (PHASE == 1) ? preAbp[0] : 0.f;
#undef TI

    int g[5], gc[5];
    bool inD[5], exS[5], exL[5];
    #pragma unroll
    for (int j = 0; j < 5; ++j) {
        const int sp = 5 * lane + j;
        g[j]  = w * OWN - HB + sp;
        inD[j] = (g[j] >= 0) && (g[j] < NN);
        const bool own = (sp >= HB) && (sp < HB + OWN);
        exS[j] = ((sp >= HB) && (sp < 2 * HB)) || ((sp >= OWN) && (sp < OWN + HB));
        exL[j] = (!own) && inD[j];
        gc[j] = g[j] < 0 ? 0 : (g[j] > NN - 1 ? NN - 1 : g[j]);
    }
    const bool edgeW = (w == 0) || (w == NW - 1);
    const int stbase = w * 160 + 5 * lane;

    float s[5], u[5], ra[5], rb[5];

    auto loadR = [&](int t, float (&r)[5]) {
        const float* row = RIN + (size_t)t * NN;
        #pragma unroll
        for (int j = 0; j < 5; ++j) r[j] = __ldg(row + gc[j]);
    };

    loadR(0, ra);
    loadR(1, rb);

    // ---- t = 0 ----
    if (PHASE == 1) {
        if (edgeW) {
            #pragma unroll
            for (int j = 0; j < 5; ++j) if (!inD[j]) ra[j] = 0.f;
        }
        #pragma unroll
        for (int j = 0; j < 5; ++j) s[j] = pAb;
        float L2, L1, R0, R1;
        HALO4(ra, L2, L1, R0, R1);
        conv5acc(s, ra, L2, L1, R0, R1, pA);
    } else {
        #pragma unroll
        for (int j = 0; j < 5; ++j) s[j] = ra[j];
    }
    #pragma unroll
    for (int j = 0; j < 5; ++j) if (!inD[j]) s[j] = 0.f;
    loadR(2, ra);

    // ---- t = 1: s_1 and u_0 ----
    {
        float sL2, sL1, sR0, sR1;
        HALO4(s, sL2, sL1, sR0, sR1);
        #pragma unroll
        for (int j = 0; j < 5; ++j) u[j] = pBb;
        conv5acc(u, s, sL2, sL1, sR0, sR1, pB);

        float a[5];
        if (PHASE == 1) {
            if (edgeW) {
                #pragma unroll
                for (int j = 0; j < 5; ++j) if (!inD[j]) rb[j] = 0.f;
            }
            #pragma unroll
            for (int j = 0; j < 5; ++j) a[j] = bA;
            float L2, L1, R0, R1;
            HALO4(rb, L2, L1, R0, R1);
            conv5acc(a, rb, L2, L1, R0, R1, aX);
        } else {
            #pragma unroll
            for (int j = 0; j < 5; ++j) a[j] = rb[j];
        }
        conv5acc(a, s, sL2, sL1, sR0, sR1, aS);

        if (edgeW) {
            #pragma unroll
            for (int j = 0; j < 5; ++j) if (!inD[j]) { a[j] = 0.f; u[j] = 0.f; }
        }
        #pragma unroll
        for (int j = 0; j < 5; ++j) s[j] = a[j];
        #pragma unroll
        for (int j = 0; j < 5; ++j) sm->stage[0][stbase + j] = u[j];
        loadR(3, rb);
    }

    // ---- main loop: tick t computes s_t and u_{t-1} ----
    auto body = [&](int t, float (&rc)[5]) {
        if (PHASE == 1 && edgeW) {
            #pragma unroll
            for (int j = 0; j < 5; ++j) if (!inD[j]) rc[j] = 0.f;
        }
        float sL2, sL1, sR0, sR1, uL2, uL1, uR0, uR1;
        HALO4(s, sL2, sL1, sR0, sR1);
        HALO4(u, uL2, uL1, uR0, uR1);

        float a[5], c[5];
        if (PHASE == 1) {
            float rL2, rL1, rR0, rR1;
            HALO4(rc, rL2, rL1, rR0, rR1);
            #pragma unroll
            for (int j = 0; j < 5; ++j) a[j] = bA;
            conv5acc(a, rc, rL2, rL1, rR0, rR1, aX);
        } else {
            #pragma unroll
            for (int j = 0; j < 5; ++j) a[j] = rc[j];
        }
        conv5acc(a, s, sL2, sL1, sR0, sR1, aS);

        #pragma unroll
        for (int j = 0; j < 5; ++j) c[j] = bB;
        conv5acc(c, u, uL2, uL1, uR0, uR1, bS);
        conv5acc(c, s, sL2, sL1, sR0, sR1, bX);

        if (edgeW) {
            #pragma unroll
            for (int j = 0; j < 5; ++j) if (!inD[j]) { a[j] = 0.f; c[j] = 0.f; }
        }
        const int sr = (t - 1) & 31;
        #pragma unroll
        for (int j = 0; j < 5; ++j) sm->stage[sr][stbase + j] = c[j];
        #pragma unroll
        for (int j = 0; j < 5; ++j) { s[j] = a[j]; u[j] = c[j]; }

        int tn = t + 2; if (tn > TT - 1) tn = TT - 1;
        loadR(tn, rc);

        if ((t & 7) == 0) {                 // exchange every 8 ticks (t = 8..1016)
            const int buf = (t >> 3) & 1;
            #pragma unroll
            for (int j = 0; j < 5; ++j) if (exS[j]) {
                sm->sEx[buf][g[j] + HB] = s[j];
                sm->uEx[buf][g[j] + HB] = u[j];
            }
            __syncthreads();
            if ((t & 15) == 0) flush16(sm, OUT, t - 16, tid);
            #pragma unroll
            for (int j = 0; j < 5; ++j) if (exL[j]) {
                s[j] = sm->sEx[buf][g[j] + HB];
                u[j] = sm->uEx[buf][g[j] + HB];
            }
        }
    };

    #pragma unroll 1
    for (int t = 2; t < TT; t += 2) { body(t, ra); body(t + 1, rb); }

    // ---- epilogue t = TT: u_{TT-1} ----
    {
        float sL2, sL1, sR0, sR1, uL2, uL1, uR0, uR1;
        HALO4(s, sL2, sL1, sR0, sR1);
        HALO4(u, uL2, uL1, uR0, uR1);
        float c[5];
        #pragma unroll
        for (int j = 0; j < 5; ++j) c[j] = bB;
        conv5acc(c, u, uL2, uL1, uR0, uR1, bS);
        conv5acc(c, s, sL2, sL1, sR0, sR1, bX);
        if (edgeW) {
            #pragma unroll
            for (int j = 0; j < 5; ++j) if (!inD[j]) c[j] = 0.f;
        }
        #pragma unroll
        for (int j = 0; j < 5; ++j) sm->stage[31][stbase + j] = c[j];
        __syncthreads();
        flush16(sm, OUT, TT - 16, tid);
        __syncthreads();
    }
}

// Y[b][0][p]   = pre1_b + conv_row(pre1, x[b][0])
// Y[b][t][p]   = c1_b  + conv_row(c1 x-channel, x[b][t])     (t >= 1)
__global__ void __launch_bounds__(256)
yprep(const float* __restrict__ x,
      const float* __restrict__ p1w, const float* __restrict__ p1b,
      const float* __restrict__ c1w, const float* __restrict__ c1b)
{
    const int r = blockIdx.x & (TT - 1);
    const int b = blockIdx.x >> 10;
    const float* xr = x + ((size_t)b * TT + r) * NN;
    float* yr = g_y + ((size_t)b * TT + r) * NN;
    float tp[5], bias;
    if (r == 0) {
        #pragma unroll
        for (int k = 0; k < 5; ++k) tp[k] = p1w[10 + k];
        bias = p1b[0];
    } else {
        #pragma unroll
        for (int k = 0; k < 5; ++k) tp[k] = c1w[35 + k];   // x-channel, row-2 taps
        bias = c1b[0];
    }
    const int p0 = threadIdx.x * 4;
    #pragma unroll
    for (int j = 0; j < 4; ++j) {
        const int p = p0 + j;
        float acc = bias;
        #pragma unroll
        for (int k = 0; k < 5; ++k) {
            const int q = p + k - 2;
            const float v = (q >= 0 && q < NN) ? __ldg(xr + q) : 0.f;
            acc = fmaf(tp[k], v, acc);
        }
        yr[p] = acc;
    }
}

__global__ void __launch_bounds__(NTH, 1)
scm_kernel(const float* __restrict__ x, float* __restrict__ out,
           const float* p1w, const float* p1b, const float* p2w, const float* p2b,
           const float* p3w, const float* p3b, const float* p4w, const float* p4b,
           const float* c1w, const float* c1b, const float* c2w, const float* c2b,
           const float* c3w, const float* c3b, const float* c4w, const float* c4b)
{
    extern __shared__ char raw[];
    Smem* sm = reinterpret_cast<Smem*>(raw);
    const int b = blockIdx.x;

    const float* Y = g_y + (size_t)b * NN * TT;
    float* scr     = g_scr + (size_t)b * NN * TT;
    float* o       = out + (size_t)b * NN * TT;

    // phase A: passes 1+2 (scan over h, row taps); x-term precomputed in Y
    fused_scan<0, 0>(sm, Y, scr, p2w, p2b, c1w, c1b, c2w, c2b, p1w, p1b);
    __syncthreads();
    // phase B: passes 3+4 (scan over w, col taps); x-term = conv of scr rows inline
    fused_scan<1, 1>(sm, scr, o, p4w, p4b, c3w, c3b, c4w, c4b, p3w, p3b);
}

extern "C" void kernel_launch(void* const* d_in, const int* in_sizes, int n_in,
                              void* d_out, int out_size)
{
    (void)in_sizes; (void)n_in; (void)out_size;
    const float* x   = (const float*)d_in[0];
    const float* p1w = (const float*)d_in[1];
    const float* p1b = (const float*)d_in[2];
    const float* p2w = (const float*)d_in[3];
    const float* p2b = (const float*)d_in[4];
    const float* p3w = (const float*)d_in[5];
    const float* p3b = (const float*)d_in[6];
    const float* p4w = (const float*)d_in[7];
    const float* p4b = (const float*)d_in[8];
    const float* c1w = (const float*)d_in[9];
    const float* c1b = (const float*)d_in[10];
    const float* c2w = (const float*)d_in[11];
    const float* c2b = (const float*)d_in[12];
    const float* c3w = (const float*)d_in[13];
    const float* c3b = (const float*)d_in[14];
    const float* c4w = (const float*)d_in[15];
    const float* c4b = (const float*)d_in[16];

    yprep<<<8 * TT, 256>>>(x, p1w, p1b, c1w, c1b);

    cudaFuncSetAttribute(scm_kernel, cudaFuncAttributeMaxDynamicSharedMemorySize,
                         (int)sizeof(Smem));
    scm_kernel<<<8, NTH, sizeof(Smem)>>>(
        x, (float*)d_out,
        p1w, p1b, p2w, p2b, p3w, p3b, p4w, p4b,
        c1w, c1b, c2w, c2b, c3w, c3b, c4w, c4b);
}

// round 5
// speedup vs baseline: 2.2606x; 1.2493x over previous
#include <cuda_runtime.h>
#include <cstdint>

// SCM_19061064860184 — cluster-distributed register scan (hardened).
// Per batch: 4-CTA cluster, each CTA 256 threads owning 256 positions.
// Warp owns 32 positions + 16-halo each side (window 64, 2 slots/thread).
// Halo exchange every 8 ticks: smem intra-CTA, DSMEM cross-CTA, split cluster
// arrive/wait with the output flush overlapped inside the wait.
// Both phases run in PHASE-0 form: s_t = convS(s_{t-1}) + R[t], R precomputed.

#define NN 1024
#define TT 1024
#define NTH 256
#define CLC 4
#define OWNC 256
#define HB 16
#define EXW (OWNC + 2 * HB)   // 288
#define SW  (8 * 66)          // 528 padded stage width
#define FULLM 0xffffffffu

struct Smem {
    float sEx[2][EXW];
    float uEx[2][EXW];
    float stage[32][SW];
};

__device__ float g_scr[8 * NN * TT];   // phase-A output (out2, transposed)
__device__ float g_R[8 * NN * TT];     // precomputed R for current phase

__device__ __forceinline__ void conv2acc(float& o0, float& o1,
    float L2, float L1, float v0, float v1, float R0, float R1, const float tp[5])
{
    o0 = fmaf(tp[0], L2, o0); o0 = fmaf(tp[1], L1, o0); o0 = fmaf(tp[2], v0, o0);
    o0 = fmaf(tp[3], v1, o0); o0 = fmaf(tp[4], R0, o0);
    o1 = fmaf(tp[0], L1, o1); o1 = fmaf(tp[1], v0, o1); o1 = fmaf(tp[2], v1, o1);
    o1 = fmaf(tp[3], R0, o1); o1 = fmaf(tp[4], R1, o1);
}

#define HALO2(v0, v1, L2, L1, R0, R1) do {        \
    L1 = __shfl_up_sync(FULLM, v1, 1);            \
    L2 = __shfl_up_sync(FULLM, v0, 1);            \
    R0 = __shfl_down_sync(FULLM, v0, 1);          \
    R1 = __shfl_down_sync(FULLM, v1, 1);          \
} while (0)

#define CLUSTER_ARRIVE() asm volatile("barrier.cluster.arrive.aligned;" ::: "memory")
#define CLUSTER_WAIT()   asm volatile("barrier.cluster.wait.aligned;"   ::: "memory")

__device__ __forceinline__ void dsm_store(float* lptr, int trank, float v)
{
    uint32_t la = (uint32_t)__cvta_generic_to_shared(lptr);
    uint32_t ra;
    asm volatile("mapa.shared::cluster.u32 %0, %1, %2;" : "=r"(ra) : "r"(la), "r"(trank));
    asm volatile("st.shared::cluster.f32 [%0], %1;" :: "r"(ra), "f"(v) : "memory");
}

// flush 16 u-rows (indices i0..i0+15) for this CTA's 256 positions,
// transposed + reversed, float4 stores
__device__ __forceinline__ void flush16(Smem* __restrict__ sm, float* __restrict__ O,
                                        int i0, int tid, int rank)
{
    const int q  = tid & 3;
    const int rt = tid >> 2;
    const int cb = NN - 4 - i0 - 4 * q;
    #pragma unroll
    for (int k = 0; k < 4; ++k) {
        const int pl = rt + (k << 6);                       // local position 0..255
        const int sa = (pl >> 5) * 66 + (pl & 31) + 16;     // stage column of pl
        float4 v;
        v.x = sm->stage[(i0 + 4 * q + 3) & 31][sa];
        v.y = sm->stage[(i0 + 4 * q + 2) & 31][sa];
        v.z = sm->stage[(i0 + 4 * q + 1) & 31][sa];
        v.w = sm->stage[(i0 + 4 * q + 0) & 31][sa];
        *reinterpret_cast<float4*>(O + (size_t)(rank * OWNC + pl) * NN + cb) = v;
    }
}

// PHASE 0: writes g_scr; PHASE 1: writes OUTparam. R always g_R.
// s_t = convS_A(s_{t-1}) + R[t]  (R includes bias + x/pre contribution)
// u_0 = preB(s_0)+pBb ; u_t = convS_B(u_{t-1}) + convX_B(s_t) + bB
template <int COLTAPS, int PHASE>
__global__ void __launch_bounds__(NTH, 1) __cluster_dims__(CLC, 1, 1)
scan_kernel(float* __restrict__ OUTparam,
            const float* __restrict__ preBw, const float* __restrict__ preBb,
            const float* __restrict__ cAw,
            const float* __restrict__ cBw, const float* __restrict__ cBb)
{
    extern __shared__ char raw[];
    Smem* sm = reinterpret_cast<Smem*>(raw);
    const int rank  = blockIdx.x & (CLC - 1);
    const int batch = blockIdx.x >> 2;
    const float* RIN = g_R + (size_t)batch * NN * TT;
    float* O = (PHASE == 0 ? g_scr : OUTparam) + (size_t)batch * NN * TT;

    const int tid = threadIdx.x, w = tid >> 5, lane = tid & 31;
#define TI(k) (COLTAPS ? (5 * (k) + 2) : (10 + (k)))
    float aS[5], bS[5], bX[5], pB[5];
    #pragma unroll
    for (int k = 0; k < 5; ++k) {
        aS[k] = cAw[TI(k)];
        bS[k] = cBw[TI(k)];
        bX[k] = cBw[25 + TI(k)];
        pB[k] = preBw[TI(k)];
    }
    const float bB = cBb[0], pBb = preBb[0];
#undef TI

    // geometry
    const int off0 = w * 32 + 2 * lane;          // CTA-window coord of slot 0 (0..286)
    const int g0   = rank * OWNC - HB + off0;    // global position of slot 0
    const bool inD0 = (g0 >= 0) && (g0 < NN);
    const bool inD1 = (g0 + 1 >= 0) && (g0 + 1 < NN);
    const bool own  = (lane >= 8 && lane < 24);
    const bool edgeW = (rank == 0 && w == 0) || (rank == CLC - 1 && w == 7);
    const bool remL = (rank > 0) && (w == 0) && (lane >= 8 && lane < 16);
    const bool remR = (rank < CLC - 1) && (w == 7) && (lane >= 16 && lane < 24);
    const int gc0 = g0 < 0 ? 0 : (g0 > NN - 1 ? NN - 1 : g0);
    const int gc1 = g0 + 1 < 0 ? 0 : (g0 + 1 > NN - 1 ? NN - 1 : g0 + 1);
    const int stb = w * 66 + 2 * lane;

    // zero exchange buffers (edge-halo slots stay 0 forever = domain padding)
    {
        float* p0 = &sm->sEx[0][0];
        float* p1 = &sm->uEx[0][0];
        for (int i = tid; i < 2 * EXW; i += NTH) { p0[i] = 0.f; p1[i] = 0.f; }
    }
    __syncthreads();
    // cluster-wide: all exchange buffers zeroed before any peer can DSMEM-store
    CLUSTER_ARRIVE();
    CLUSTER_WAIT();

    float s0, s1, u0, u1, ra0, ra1, rb0, rb1;
    ra0 = __ldg(RIN + gc0);       ra1 = __ldg(RIN + gc1);
    rb0 = __ldg(RIN + NN + gc0);  rb1 = __ldg(RIN + NN + gc1);

    // t = 0
    s0 = inD0 ? ra0 : 0.f;
    s1 = inD1 ? ra1 : 0.f;
    ra0 = __ldg(RIN + 2 * NN + gc0); ra1 = __ldg(RIN + 2 * NN + gc1);

    // t = 1: s_1 = convS(s_0) + R[1] ; u_0 = preB(s_0)
    {
        float sL2, sL1, sR0, sR1;
        HALO2(s0, s1, sL2, sL1, sR0, sR1);
        float a0 = rb0, a1 = rb1;
        conv2acc(a0, a1, sL2, sL1, s0, s1, sR0, sR1, aS);
        float c0 = pBb, c1 = pBb;
        conv2acc(c0, c1, sL2, sL1, s0, s1, sR0, sR1, pB);
        if (edgeW) {
            if (!inD0) { a0 = 0.f; c0 = 0.f; }
            if (!inD1) { a1 = 0.f; c1 = 0.f; }
        }
        s0 = a0; s1 = a1; u0 = c0; u1 = c1;
        sm->stage[0][stb] = u0; sm->stage[0][stb + 1] = u1;
        rb0 = __ldg(RIN + 3 * NN + gc0); rb1 = __ldg(RIN + 3 * NN + gc1);
    }

    // main loop: tick t computes s_t and u_{t-1}
    auto body = [&](int t, float& rc0, float& rc1) {
        float sL2, sL1, sR0, sR1, uL2, uL1, uR0, uR1;
        HALO2(s0, s1, sL2, sL1, sR0, sR1);
        HALO2(u0, u1, uL2, uL1, uR0, uR1);

        float a0 = rc0, a1 = rc1;
        conv2acc(a0, a1, sL2, sL1, s0, s1, sR0, sR1, aS);
        float c0 = bB, c1 = bB;
        conv2acc(c0, c1, uL2, uL1, u0, u1, uR0, uR1, bS);
        conv2acc(c0, c1, sL2, sL1, s0, s1, sR0, sR1, bX);

        if (edgeW) {
            if (!inD0) { a0 = 0.f; c0 = 0.f; }
            if (!inD1) { a1 = 0.f; c1 = 0.f; }
        }
        const int sr = (t - 1) & 31;
        sm->stage[sr][stb] = c0; sm->stage[sr][stb + 1] = c1;
        s0 = a0; s1 = a1; u0 = c0; u1 = c1;

        int tn = t + 2; if (tn > TT - 1) tn = TT - 1;
        rc0 = __ldg(RIN + (size_t)tn * NN + gc0);
        rc1 = __ldg(RIN + (size_t)tn * NN + gc1);

        if ((t & 7) == 0) {                       // exchange epoch
            const int buf = (t >> 3) & 1;
            if (own) {
                sm->sEx[buf][off0] = s0; sm->sEx[buf][off0 + 1] = s1;
                sm->uEx[buf][off0] = u0; sm->uEx[buf][off0 + 1] = u1;
            }
            if (remL) {                           // my first 16 own -> left CTA's right halo
                dsm_store(&sm->sEx[buf][off0 + 256], rank - 1, s0);
                dsm_store(&sm->sEx[buf][off0 + 257], rank - 1, s1);
                dsm_store(&sm->uEx[buf][off0 + 256], rank - 1, u0);
                dsm_store(&sm->uEx[buf][off0 + 257], rank - 1, u1);
            }
            if (remR) {                           // my last 16 own -> right CTA's left halo
                dsm_store(&sm->sEx[buf][off0 - 256], rank + 1, s0);
                dsm_store(&sm->sEx[buf][off0 - 255], rank + 1, s1);
                dsm_store(&sm->uEx[buf][off0 - 256], rank + 1, u0);
                dsm_store(&sm->uEx[buf][off0 - 255], rank + 1, u1);
            }
            __syncthreads();                      // local stage + sEx visible CTA-wide
            CLUSTER_ARRIVE();
            if ((t & 15) == 0) flush16(sm, O, t - 16, tid, rank);  // overlap with wait
            CLUSTER_WAIT();
            if (!own) {
                if (inD0) { s0 = sm->sEx[buf][off0];     u0 = sm->uEx[buf][off0]; }
                if (inD1) { s1 = sm->sEx[buf][off0 + 1]; u1 = sm->uEx[buf][off0 + 1]; }
            }
        }
    };

    #pragma unroll 1
    for (int t = 2; t < TT; t += 2) { body(t, ra0, ra1); body(t + 1, rb0, rb1); }

    // epilogue t = TT: u_{TT-1}
    {
        float sL2, sL1, sR0, sR1, uL2, uL1, uR0, uR1;
        HALO2(s0, s1, sL2, sL1, sR0, sR1);
        HALO2(u0, u1, uL2, uL1, uR0, uR1);
        float c0 = bB, c1 = bB;
        conv2acc(c0, c1, uL2, uL1, u0, u1, uR0, uR1, bS);
        conv2acc(c0, c1, sL2, sL1, s0, s1, sR0, sR1, bX);
        if (edgeW) { if (!inD0) c0 = 0.f; if (!inD1) c1 = 0.f; }
        sm->stage[31][stb] = c0; sm->stage[31][stb + 1] = c1;
        __syncthreads();
        flush16(sm, O, TT - 16, tid, rank);
    }
}

// R[b][0][p] = pre_b + conv(pre taps, src[b][0]) ; R[b][t][p] = c_b + conv(c x-taps, src[b][t])
template <int COLTAPS, int PHASE>
__global__ void __launch_bounds__(256)
yprep(const float* __restrict__ srcparam,
      const float* __restrict__ pw, const float* __restrict__ pb,
      const float* __restrict__ cw, const float* __restrict__ cbias)
{
    const int r = blockIdx.x & (TT - 1);
    const int b = blockIdx.x >> 10;
    const float* src = (PHASE == 0 ? srcparam : (const float*)g_scr);
    const float* xr = src + ((size_t)b * TT + r) * NN;
    float* yr = g_R + ((size_t)b * TT + r) * NN;
    float tp[5], bias;
    #pragma unroll
    for (int k = 0; k < 5; ++k) {
        const int ti = COLTAPS ? (5 * k + 2) : (10 + k);
        tp[k] = (r == 0) ? pw[ti] : cw[25 + ti];
    }
    bias = (r == 0) ? pb[0] : cbias[0];
    const int p0 = threadIdx.x * 4;
    #pragma unroll
    for (int j = 0; j < 4; ++j) {
        const int p = p0 + j;
        float acc = bias;
        #pragma unroll
        for (int k = 0; k < 5; ++k) {
            const int q = p + k - 2;
            const float v = (q >= 0 && q < NN) ? __ldg(xr + q) : 0.f;
            acc = fmaf(tp[k], v, acc);
        }
        yr[p] = acc;
    }
}

extern "C" void kernel_launch(void* const* d_in, const int* in_sizes, int n_in,
                              void* d_out, int out_size)
{
    (void)in_sizes; (void)n_in; (void)out_size;
    const float* x   = (const float*)d_in[0];
    const float* p1w = (const float*)d_in[1];
    const float* p1b = (const float*)d_in[2];
    const float* p2w = (const float*)d_in[3];
    const float* p2b = (const float*)d_in[4];
    const float* p3w = (const float*)d_in[5];
    const float* p3b = (const float*)d_in[6];
    const float* p4w = (const float*)d_in[7];
    const float* p4b = (const float*)d_in[8];
    const float* c1w = (const float*)d_in[9];
    const float* c1b = (const float*)d_in[10];
    const float* c2w = (const float*)d_in[11];
    const float* c2b = (const float*)d_in[12];
    const float* c3w = (const float*)d_in[13];
    const float* c3b = (const float*)d_in[14];
    const float* c4w = (const float*)d_in[15];
    const float* c4b = (const float*)d_in[16];

    cudaFuncSetAttribute(scan_kernel<0, 0>, cudaFuncAttributeMaxDynamicSharedMemorySize, (int)sizeof(Smem));
    cudaFuncSetAttribute(scan_kernel<1, 1>, cudaFuncAttributeMaxDynamicSharedMemorySize, (int)sizeof(Smem));

    // phase A: R = pre1/c1-x conv of x rows; scan (row taps) -> g_scr
    yprep<0, 0><<<8 * TT, 256>>>(x, p1w, p1b, c1w, c1b);
    scan_kernel<0, 0><<<8 * CLC, NTH, sizeof(Smem)>>>(nullptr, p2w, p2b, c1w, c2w, c2b);
    // phase B: R = pre3/c3-x conv of scr rows; scan (col taps) -> out
    yprep<1, 1><<<8 * TT, 256>>>(nullptr, p3w, p3b, c3w, c3b);
    scan_kernel<1, 1><<<8 * CLC, NTH, sizeof(Smem)>>>((float*)d_out, p4w, p4b, c3w, c4w, c4b);
}

// round 6
// speedup vs baseline: 2.7713x; 1.2259x over previous
#include <cuda_runtime.h>
#include <cstdint>

// SCM_19061064860184 — cluster-distributed register scan, R6:
// depth-4 register prefetch of R, 2-wide vectorized loads/stores, split u-chains.
// Per batch: 4-CTA cluster, 256 threads/CTA owning 256 positions.
// Warp owns 32 positions + 16-halo each side (window 64, 2 slots/thread).
// Halo exchange every 8 ticks (smem + DSMEM + split cluster arrive/wait).

#define NN 1024
#define TT 1024
#define NTH 256
#define CLC 4
#define OWNC 256
#define HB 16
#define EXW (OWNC + 2 * HB)   // 288
#define SW  (8 * 66)          // 528 padded stage width
#define FULLM 0xffffffffu

struct alignas(16) Smem {
    float sEx[2][EXW];
    float uEx[2][EXW];
    float stage[32][SW];
};

__device__ float g_scr[8 * NN * TT];            // phase-A output (out2, transposed)
__device__ float g_R[8 * NN * TT + 4 * NN];     // precomputed R (+4 pad rows for prefetch)

__device__ __forceinline__ void conv2acc(float& o0, float& o1,
    float L2, float L1, float v0, float v1, float R0, float R1, const float tp[5])
{
    o0 = fmaf(tp[0], L2, o0); o0 = fmaf(tp[1], L1, o0); o0 = fmaf(tp[2], v0, o0);
    o0 = fmaf(tp[3], v1, o0); o0 = fmaf(tp[4], R0, o0);
    o1 = fmaf(tp[0], L1, o1); o1 = fmaf(tp[1], v0, o1); o1 = fmaf(tp[2], v1, o1);
    o1 = fmaf(tp[3], R0, o1); o1 = fmaf(tp[4], R1, o1);
}

#define HALO2(v0, v1, L2, L1, R0, R1) do {        \
    L1 = __shfl_up_sync(FULLM, v1, 1);            \
    L2 = __shfl_up_sync(FULLM, v0, 1);            \
    R0 = __shfl_down_sync(FULLM, v0, 1);          \
    R1 = __shfl_down_sync(FULLM, v1, 1);          \
} while (0)

#define CLUSTER_ARRIVE() asm volatile("barrier.cluster.arrive.aligned;" ::: "memory")
#define CLUSTER_WAIT()   asm volatile("barrier.cluster.wait.aligned;"   ::: "memory")

__device__ __forceinline__ void dsm_store2(float* lptr, int trank, float a, float b)
{
    uint32_t la = (uint32_t)__cvta_generic_to_shared(lptr);
    uint32_t ra;
    asm volatile("mapa.shared::cluster.u32 %0, %1, %2;" : "=r"(ra) : "r"(la), "r"(trank));
    asm volatile("st.shared::cluster.v2.f32 [%0], {%1, %2};"
                 :: "r"(ra), "f"(a), "f"(b) : "memory");
}

// flush 16 u-rows (indices i0..i0+15) for this CTA's 256 positions,
// transposed + reversed, float4 stores
__device__ __forceinline__ void flush16(Smem* __restrict__ sm, float* __restrict__ O,
                                        int i0, int tid, int rank)
{
    const int q  = tid & 3;
    const int rt = tid >> 2;
    const int cb = NN - 4 - i0 - 4 * q;
    #pragma unroll
    for (int k = 0; k < 4; ++k) {
        const int pl = rt + (k << 6);                       // local position 0..255
        const int sa = (pl >> 5) * 66 + (pl & 31) + 16;     // stage column of pl
        float4 v;
        v.x = sm->stage[(i0 + 4 * q + 3) & 31][sa];
        v.y = sm->stage[(i0 + 4 * q + 2) & 31][sa];
        v.z = sm->stage[(i0 + 4 * q + 1) & 31][sa];
        v.w = sm->stage[(i0 + 4 * q + 0) & 31][sa];
        *reinterpret_cast<float4*>(O + (size_t)(rank * OWNC + pl) * NN + cb) = v;
    }
}

// PHASE 0: writes g_scr; PHASE 1: writes OUTparam. R always g_R.
// s_t = convS_A(s_{t-1}) + R[t]  (R includes bias + x/pre contribution)
// u_0 = preB(s_0)+pBb ; u_t = convS_B(u_{t-1}) + convX_B(s_t) + bB
template <int COLTAPS, int PHASE>
__global__ void __launch_bounds__(NTH, 1) __cluster_dims__(CLC, 1, 1)
scan_kernel(float* __restrict__ OUTparam,
            const float* __restrict__ preBw, const float* __restrict__ preBb,
            const float* __restrict__ cAw,
            const float* __restrict__ cBw, const float* __restrict__ cBb)
{
    extern __shared__ char raw[];
    Smem* sm = reinterpret_cast<Smem*>(raw);
    const int rank  = blockIdx.x & (CLC - 1);
    const int batch = blockIdx.x >> 2;
    const float* RIN = g_R + (size_t)batch * NN * TT;
    float* O = (PHASE == 0 ? g_scr : OUTparam) + (size_t)batch * NN * TT;

    const int tid = threadIdx.x, w = tid >> 5, lane = tid & 31;
#define TI(k) (COLTAPS ? (5 * (k) + 2) : (10 + (k)))
    float aS[5], bS[5], bX[5], pB[5];
    #pragma unroll
    for (int k = 0; k < 5; ++k) {
        aS[k] = cAw[TI(k)];
        bS[k] = cBw[TI(k)];
        bX[k] = cBw[25 + TI(k)];
        pB[k] = preBw[TI(k)];
    }
    const float bB = cBb[0], pBb = preBb[0];
#undef TI

    // geometry
    const int off0 = w * 32 + 2 * lane;          // CTA-window coord of slot 0 (0..286)
    const int g0   = rank * OWNC - HB + off0;    // global position of slot 0
    const bool inD0 = (g0 >= 0) && (g0 < NN);
    const bool inD1 = (g0 + 1 >= 0) && (g0 + 1 < NN);
    const bool own  = (lane >= 8 && lane < 24);
    const bool edgeW = (rank == 0 && w == 0) || (rank == CLC - 1 && w == 7);
    const bool remL = (rank > 0) && (w == 0) && (lane >= 8 && lane < 16);
    const bool remR = (rank < CLC - 1) && (w == 7) && (lane >= 16 && lane < 24);
    const int gr = g0 < 0 ? 0 : (g0 > NN - 2 ? NN - 2 : g0);   // float2-safe clamp
    const int stb = w * 66 + 2 * lane;

    // zero exchange buffers (edge-halo slots stay 0 forever = domain padding)
    {
        float* p0 = &sm->sEx[0][0];
        float* p1 = &sm->uEx[0][0];
        for (int i = tid; i < 2 * EXW; i += NTH) { p0[i] = 0.f; p1[i] = 0.f; }
    }
    __syncthreads();
    // cluster-wide: all exchange buffers zeroed before any peer can DSMEM-store
    CLUSTER_ARRIVE();
    CLUSTER_WAIT();

    // depth-4 prefetch ring; rows 0..5 live in ra,rb,rr0..rr3
    const float2* rp = reinterpret_cast<const float2*>(RIN + gr);
    const int RSTEP = NN / 2;                    // one row, in float2 units
    float2 ra  = rp[0];
    float2 rb  = rp[RSTEP];
    float2 rr0 = rp[2 * RSTEP];
    float2 rr1 = rp[3 * RSTEP];
    float2 rr2 = rp[4 * RSTEP];
    float2 rr3 = rp[5 * RSTEP];
    const float2* pf = rp + 6 * RSTEP;           // next row to prefetch (row 6)

    float s0, s1, u0, u1;

    // t = 0
    s0 = inD0 ? ra.x : 0.f;
    s1 = inD1 ? ra.y : 0.f;

    // t = 1: s_1 = convS(s_0) + R[1] ; u_0 = preB(s_0)
    {
        float sL2, sL1, sR0, sR1;
        HALO2(s0, s1, sL2, sL1, sR0, sR1);
        float a0 = rb.x, a1 = rb.y;
        conv2acc(a0, a1, sL2, sL1, s0, s1, sR0, sR1, aS);
        float c0 = pBb, c1 = pBb;
        conv2acc(c0, c1, sL2, sL1, s0, s1, sR0, sR1, pB);
        if (edgeW) {
            if (!inD0) { a0 = 0.f; c0 = 0.f; }
            if (!inD1) { a1 = 0.f; c1 = 0.f; }
        }
        s0 = a0; s1 = a1; u0 = c0; u1 = c1;
        *reinterpret_cast<float2*>(&sm->stage[0][stb]) = make_float2(u0, u1);
    }

    // main body: tick t computes s_t and u_{t-1}; prefetches row t+4 into rc
    auto body = [&](int t, float2& rc, const float2* ld) {
        float sL2, sL1, sR0, sR1, uL2, uL1, uR0, uR1;
        HALO2(s0, s1, sL2, sL1, sR0, sR1);
        HALO2(u0, u1, uL2, uL1, uR0, uR1);

        float a0 = rc.x, a1 = rc.y;
        conv2acc(a0, a1, sL2, sL1, s0, s1, sR0, sR1, aS);
        float cu0 = bB, cu1 = bB;                         // u-tap chain
        conv2acc(cu0, cu1, uL2, uL1, uR0 == uR0 ? u0 : u0, u1, uR0, uR1, bS);
        float cs0 = 0.f, cs1 = 0.f;                       // s-tap chain (independent)
        conv2acc(cs0, cs1, sL2, sL1, s0, s1, sR0, sR1, bX);
        float c0 = cu0 + cs0, c1 = cu1 + cs1;

        if (edgeW) {
            if (!inD0) { a0 = 0.f; c0 = 0.f; }
            if (!inD1) { a1 = 0.f; c1 = 0.f; }
        }
        const int sr = (t - 1) & 31;
        *reinterpret_cast<float2*>(&sm->stage[sr][stb]) = make_float2(c0, c1);
        s0 = a0; s1 = a1; u0 = c0; u1 = c1;

        rc = *ld;                                          // prefetch row t+4

        if ((t & 7) == 0) {                       // exchange epoch
            const int buf = (t >> 3) & 1;
            if (own) {
                *reinterpret_cast<float2*>(&sm->sEx[buf][off0]) = make_float2(s0, s1);
                *reinterpret_cast<float2*>(&sm->uEx[buf][off0]) = make_float2(u0, u1);
            }
            if (remL) {                           // my first 16 own -> left CTA's right halo
                dsm_store2(&sm->sEx[buf][off0 + 256], rank - 1, s0, s1);
                dsm_store2(&sm->uEx[buf][off0 + 256], rank - 1, u0, u1);
            }
            if (remR) {                           // my last 16 own -> right CTA's left halo
                dsm_store2(&sm->sEx[buf][off0 - 256], rank + 1, s0, s1);
                dsm_store2(&sm->uEx[buf][off0 - 256], rank + 1, u0, u1);
            }
            __syncthreads();                      // local stage + sEx visible CTA-wide
            CLUSTER_ARRIVE();
            if ((t & 15) == 0) flush16(sm, O, t - 16, tid, rank);  // overlap with wait
            CLUSTER_WAIT();
            if (!own) {
                if (inD0) {
                    float2 sv = *reinterpret_cast<const float2*>(&sm->sEx[buf][off0]);
                    float2 uv = *reinterpret_cast<const float2*>(&sm->uEx[buf][off0]);
                    s0 = sv.x; u0 = uv.x;
                    if (inD1) { s1 = sv.y; u1 = uv.y; }
                } else if (inD1) {
                    s1 = sm->sEx[buf][off0 + 1]; u1 = sm->uEx[buf][off0 + 1];
                }
            }
        }
    };

    // t = 2 .. 1021, unrolled x4 (1020 ticks = 255 iterations)
    #pragma unroll 1
    for (int t = 2; t <= TT - 6; t += 4) {
        body(t,     rr0, pf);
        body(t + 1, rr1, pf + RSTEP);
        body(t + 2, rr2, pf + 2 * RSTEP);
        body(t + 3, rr3, pf + 3 * RSTEP);
        pf += 4 * RSTEP;
    }
    // t = 1022, 1023 (prefetches read padded rows 1026/1027)
    body(TT - 2, rr0, pf);
    body(TT - 1, rr1, pf + RSTEP);

    // epilogue t = TT: u_{TT-1}
    {
        float sL2, sL1, sR0, sR1, uL2, uL1, uR0, uR1;
        HALO2(s0, s1, sL2, sL1, sR0, sR1);
        HALO2(u0, u1, uL2, uL1, uR0, uR1);
        float cu0 = bB, cu1 = bB;
        conv2acc(cu0, cu1, uL2, uL1, u0, u1, uR0, uR1, bS);
        float cs0 = 0.f, cs1 = 0.f;
        conv2acc(cs0, cs1, sL2, sL1, s0, s1, sR0, sR1, bX);
        float c0 = cu0 + cs0, c1 = cu1 + cs1;
        if (edgeW) { if (!inD0) c0 = 0.f; if (!inD1) c1 = 0.f; }
        *reinterpret_cast<float2*>(&sm->stage[31][stb]) = make_float2(c0, c1);
        __syncthreads();
        flush16(sm, O, TT - 16, tid, rank);
    }
}

// R[b][0][p] = pre_b + conv(pre taps, src[b][0]) ; R[b][t][p] = c_b + conv(c x-taps, src[b][t])
template <int COLTAPS, int PHASE>
__global__ void __launch_bounds__(256)
yprep(const float* __restrict__ srcparam,
      const float* __restrict__ pw, const float* __restrict__ pb,
      const float* __restrict__ cw, const float* __restrict__ cbias)
{
    const int r = blockIdx.x & (TT - 1);
    const int b = blockIdx.x >> 10;
    const float* src = (PHASE == 0 ? srcparam : (const float*)g_scr);
    const float* xr = src + ((size_t)b * TT + r) * NN;
    float* yr = g_R + ((size_t)b * TT + r) * NN;
    float tp[5], bias;
    #pragma unroll
    for (int k = 0; k < 5; ++k) {
        const int ti = COLTAPS ? (5 * k + 2) : (10 + k);
        tp[k] = (r == 0) ? pw[ti] : cw[25 + ti];
    }
    bias = (r == 0) ? pb[0] : cbias[0];
    const int p0 = threadIdx.x * 4;
    #pragma unroll
    for (int j = 0; j < 4; ++j) {
        const int p = p0 + j;
        float acc = bias;
        #pragma unroll
        for (int k = 0; k < 5; ++k) {
            const int q = p + k - 2;
            const float v = (q >= 0 && q < NN) ? __ldg(xr + q) : 0.f;
            acc = fmaf(tp[k], v, acc);
        }
        yr[p] = acc;
    }
}

extern "C" void kernel_launch(void* const* d_in, const int* in_sizes, int n_in,
                              void* d_out, int out_size)
{
    (void)in_sizes; (void)n_in; (void)out_size;
    const float* x   = (const float*)d_in[0];
    const float* p1w = (const float*)d_in[1];
    const float* p1b = (const float*)d_in[2];
    const float* p2w = (const float*)d_in[3];
    const float* p2b = (const float*)d_in[4];
    const float* p3w = (const float*)d_in[5];
    const float* p3b = (const float*)d_in[6];
    const float* p4w = (const float*)d_in[7];
    const float* p4b = (const float*)d_in[8];
    const float* c1w = (const float*)d_in[9];
    const float* c1b = (const float*)d_in[10];
    const float* c2w = (const float*)d_in[11];
    const float* c2b = (const float*)d_in[12];
    const float* c3w = (const float*)d_in[13];
    const float* c3b = (const float*)d_in[14];
    const float* c4w = (const float*)d_in[15];
    const float* c4b = (const float*)d_in[16];

    cudaFuncSetAttribute(scan_kernel<0, 0>, cudaFuncAttributeMaxDynamicSharedMemorySize, (int)sizeof(Smem));
    cudaFuncSetAttribute(scan_kernel<1, 1>, cudaFuncAttributeMaxDynamicSharedMemorySize, (int)sizeof(Smem));

    // phase A: R = pre1/c1-x conv of x rows; scan (row taps) -> g_scr
    yprep<0, 0><<<8 * TT, 256>>>(x, p1w, p1b, c1w, c1b);
    scan_kernel<0, 0><<<8 * CLC, NTH, sizeof(Smem)>>>(nullptr, p2w, p2b, c1w, c2w, c2b);
    // phase B: R = pre3/c3-x conv of scr rows; scan (col taps) -> out
    yprep<1, 1><<<8 * TT, 256>>>(nullptr, p3w, p3b, c3w, c3b);
    scan_kernel<1, 1><<<8 * CLC, NTH, sizeof(Smem)>>>((float*)d_out, p4w, p4b, c3w, c4w, c4b);
}